// round 11
// baseline (speedup 1.0000x reference)
#include <cuda_runtime.h>
#include <cuda_bf16.h>
#include <cstdint>

// LocallyConnected2d: out[b,o,y,x] = sum_{c,k} x[b,c,y+i,x+j] * w[o,c,y,x,k]
// B=16, C_IN=16, C_OUT=16, H=W=64, OH=OW=62, K=3x3.
//
// R11 = R9 compute core (best: 128 thr, 8b x 4o per thread, LDS.128 x quads,
// 16B cp.async w, triple buffer, c-split 4) + flagged epilogue: z=0 blocks
// STG partials directly (no memset of out needed) and release a per-tile
// flag; z>=1 blocks spin then atomicAdd. Deterministic (store + 3 commutative
// adds). Replaces the 3.9MB memset pre-pass with a 248-int flag clear.

#define B_  16
#define CIN 16
#define CO  16
#define H_  64
#define W_  64
#define OH_ 62
#define OW_ 62
#define TX  16
#define NT  128

#define NC  4                       // channels per block (4-way c split)
#define WROW 148                    // weight smem row stride (floats, 16B mult)
#define WBUF (CO * WROW)            // 2368 floats
#define XBUF (4 * 3 * 80)           // 960 floats: [bquad][row][col*4 + bl]
#define BQS  240                    // bquad stride (floats)

#define WOSTRIDE (CIN * OH_ * OW_ * 9)   // weight float stride per o
#define WCSTRIDE (OH_ * OW_ * 9)         // weight float stride per c
#define XCSTRIDE (H_ * W_)               // x float stride per c

#define NTILE (4 * OH_)             // 248 tiles

__device__ int g_flags[NTILE];

__device__ __forceinline__ void ffma2(unsigned long long& d,
                                      unsigned long long a,
                                      unsigned long long b) {
    asm("fma.rn.f32x2 %0, %1, %2, %0;" : "+l"(d) : "l"(a), "l"(b));
}

__device__ __forceinline__ unsigned long long bcast2(float v) {
    unsigned long long p;
    asm("mov.b64 %0, {%1, %1};" : "=l"(p) : "f"(v));
    return p;
}

__device__ __forceinline__ void cp_async16(uint32_t dst, const float* src) {
    asm volatile("cp.async.cg.shared.global [%0], [%1], 16;\n"
                 :: "r"(dst), "l"(src));
}

__device__ __forceinline__ void cp_async4(uint32_t dst, const float* src, int sz) {
    asm volatile("cp.async.ca.shared.global [%0], [%1], 4, %2;\n"
                 :: "r"(dst), "l"(src), "r"(sz));
}

__global__ void clear_flags_kernel() {
    if (threadIdx.x < NTILE) g_flags[threadIdx.x] = 0;
}

__global__ __launch_bounds__(NT, 5)
void lc2d_kernel(const float* __restrict__ xin,
                 const float* __restrict__ wgt,
                 float* __restrict__ out) {
    __shared__ __align__(16) float sh_w[3 * WBUF];
    __shared__ __align__(16) float sh_x[3 * XBUF];

    const int tid = threadIdx.x;
    const int xl  = tid & 15;
    const int grp = tid >> 4;      // 0..7
    const int bh  = grp & 1;       // b half
    const int ob  = grp >> 1;      // o group

    const int y    = blockIdx.y;
    const int x0   = blockIdx.x * TX;
    const int xt   = min(TX, OW_ - x0);     // 16 or 14
    const int zz   = blockIdx.z;
    const int c0   = zz * NC;
    const int tile = blockIdx.y * 4 + blockIdx.x;
    const int sh   = 2 * (y & 1);           // uniform 16B-alignment shift

    const uint32_t shw_base = (uint32_t)__cvta_generic_to_shared(sh_w);
    const uint32_t shx_base = (uint32_t)__cvta_generic_to_shared(sh_x);

    // ---- weight staging descriptors (16B chunks, 5 slots) ----
    const int rowch  = (xt == TX) ? 37 : 32;
    const int nchunk = CO * rowch;
    const float* wcbase = wgt + (((c0 * OH_ + y) * OW_ + x0) * 9) - sh;

    int      wsoff[5];
    uint32_t wdst[5];
    bool     wok[5];
    #pragma unroll
    for (int n = 0; n < 5; ++n) {
        int m = tid + NT * n;
        wok[n] = (m < nchunk);
        int o   = m / rowch;
        int ci4 = (m - o * rowch) * 4;
        if (o > 15) { o = 15; ci4 = 0; }
        wsoff[n] = o * WOSTRIDE + ci4;
        wdst[n]  = (uint32_t)(o * WROW + ci4) * 4;
    }

    // ---- x staging descriptors (4B, b-quad interleaved, 7 slots) ----
    int      xsrcoff[7], xsz[7];
    uint32_t xdst[7];
    bool     xvalid[7];
    #pragma unroll
    for (int n = 0; n < 7; ++n) {
        int m = tid + NT * n;
        xvalid[n] = (m < B_ * 54);
        int b   = m / 54;
        int rem = m - b * 54;
        int r   = rem / 18;
        int cc  = rem - r * 18;
        if (!xvalid[n]) { b = 0; r = 0; cc = 0; }
        bool ok = xvalid[n] && (x0 + cc < W_);
        xsrcoff[n] = (b * CIN) * XCSTRIDE + r * W_ + cc;
        xsz[n]     = ok ? 4 : 0;
        xdst[n] = (uint32_t)((b >> 2) * BQS + r * 80 + cc * 4 + (b & 3)) * 4;
    }
    const float* xbase = xin + (c0 * H_ + y) * W_ + x0;

    unsigned long long acc[4][2][2];    // [oo][q][pair]: b=(bh*2+q)*4+2*pair
    #pragma unroll
    for (int oo = 0; oo < 4; ++oo)
        #pragma unroll
        for (int q = 0; q < 2; ++q) { acc[oo][q][0] = 0ull; acc[oo][q][1] = 0ull; }

    auto stage = [&](int buf, int ci) {
        uint32_t wb = shw_base + (uint32_t)buf * (WBUF * 4);
        const float* wc = wcbase + ci * WCSTRIDE;
        #pragma unroll
        for (int n = 0; n < 5; ++n)
            if (wok[n]) cp_async16(wb + wdst[n], wc + wsoff[n]);
        uint32_t xb = shx_base + (uint32_t)buf * (XBUF * 4);
        const float* xc = xbase + ci * XCSTRIDE;
        #pragma unroll
        for (int n = 0; n < 7; ++n)
            if (xvalid[n])
                cp_async4(xb + xdst[n], xc + xsrcoff[n], xsz[n]);
        asm volatile("cp.async.commit_group;\n" ::: "memory");
    };

    stage(0, 0);
    stage(1, 1);

    int rd = 0;
    #pragma unroll 1
    for (int ci = 0; ci < NC; ++ci) {
        if (ci < NC - 1) {
            asm volatile("cp.async.wait_group 1;\n" ::: "memory");
        } else {
            asm volatile("cp.async.wait_group 0;\n" ::: "memory");
        }
        __syncthreads();

        if (ci + 2 < NC) {
            int st = rd - 1; if (st < 0) st += 3;
            stage(st, ci + 2);
        }

        const float* swb = sh_w + rd * WBUF + sh;
        const float* sxb = sh_x + rd * XBUF + bh * (2 * BQS);

        #pragma unroll
        for (int k = 0; k < 9; ++k) {
            const int i = k / 3;
            const int j = k - i * 3;
            const float* xp = &sxb[i * 80 + (xl + j) * 4];
            ulonglong2 xq0 = *reinterpret_cast<const ulonglong2*>(xp);
            ulonglong2 xq1 = *reinterpret_cast<const ulonglong2*>(xp + BQS);
            #pragma unroll
            for (int oo = 0; oo < 4; ++oo) {
                float wv = swb[(ob * 4 + oo) * WROW + xl * 9 + k];
                unsigned long long wb2 = bcast2(wv);
                ffma2(acc[oo][0][0], xq0.x, wb2);
                ffma2(acc[oo][0][1], xq0.y, wb2);
                ffma2(acc[oo][1][0], xq1.x, wb2);
                ffma2(acc[oo][1][1], xq1.y, wb2);
            }
        }

        ++rd; if (rd == 3) rd = 0;
    }

    // ---- epilogue ----
    if (zz == 0) {
        // producer: plain stores (out needs no pre-zeroing), then release flag
        if (xl < xt) {
            #pragma unroll
            for (int oo = 0; oo < 4; ++oo) {
                const int o = ob * 4 + oo;
                #pragma unroll
                for (int q = 0; q < 2; ++q) {
                    const int bq = (bh * 2 + q) * 4;
                    #pragma unroll
                    for (int p = 0; p < 2; ++p) {
                        float lo, hi;
                        asm("mov.b64 {%0, %1}, %2;"
                            : "=f"(lo), "=f"(hi) : "l"(acc[oo][q][p]));
                        const int b = bq + 2 * p;
                        out[((b * CO + o)       * OH_ + y) * OW_ + x0 + xl] = lo;
                        out[(((b + 1) * CO + o) * OH_ + y) * OW_ + x0 + xl] = hi;
                    }
                }
            }
        }
        __threadfence();
        __syncthreads();
        if (tid == 0)
            atomicExch(&g_flags[tile], 1);
    } else {
        // consumer: wait for producer's stores, then accumulate atomically
        if (tid == 0) {
            int f;
            do {
                asm volatile("ld.acquire.gpu.global.b32 %0, [%1];"
                             : "=r"(f) : "l"(&g_flags[tile]) : "memory");
            } while (f == 0);
        }
        __syncthreads();
        if (xl < xt) {
            #pragma unroll
            for (int oo = 0; oo < 4; ++oo) {
                const int o = ob * 4 + oo;
                #pragma unroll
                for (int q = 0; q < 2; ++q) {
                    const int bq = (bh * 2 + q) * 4;
                    #pragma unroll
                    for (int p = 0; p < 2; ++p) {
                        float lo, hi;
                        asm("mov.b64 {%0, %1}, %2;"
                            : "=f"(lo), "=f"(hi) : "l"(acc[oo][q][p]));
                        const int b = bq + 2 * p;
                        atomicAdd(&out[((b * CO + o)       * OH_ + y) * OW_ + x0 + xl], lo);
                        atomicAdd(&out[(((b + 1) * CO + o) * OH_ + y) * OW_ + x0 + xl], hi);
                    }
                }
            }
        }
    }
}

extern "C" void kernel_launch(void* const* d_in, const int* in_sizes, int n_in,
                              void* d_out, int out_size) {
    const float* x = (const float*)d_in[0];
    const float* w = (const float*)d_in[1];
    float* out = (float*)d_out;

    clear_flags_kernel<<<1, 256>>>();

    dim3 grid((OW_ + TX - 1) / TX, OH_, 4);   // (4, 62, 4) = 992 blocks
    lc2d_kernel<<<grid, NT>>>(x, w, out);
}

// round 12
// speedup vs baseline: 1.0567x; 1.0567x over previous
#include <cuda_runtime.h>
#include <cuda_bf16.h>
#include <cstdint>

// LocallyConnected2d: out[b,o,y,x] = sum_{c,k} x[b,c,y+i,x+j] * w[o,c,y,x,k]
// B=16, C_IN=16, C_OUT=16, H=W=64, OH=OW=62, K=3x3.
//
// R12 = R9 compute core (best: 128 thr, 8b x 4o per thread, LDS.128 x quads,
// 16B cp.async w, triple buffer, c-split 4) with an atomic-free reduction:
// z=0 blocks STG partials to out, z=1..3 to private __device__ scratch
// buffers; a float4 sum kernel then does out += s0+s1+s2 in fixed order.
// No memset, no atomics, bitwise deterministic.

#define B_  16
#define CIN 16
#define CO  16
#define H_  64
#define W_  64
#define OH_ 62
#define OW_ 62
#define TX  16
#define NT  128

#define NC  4                       // channels per block (4-way c split)
#define WROW 148                    // weight smem row stride (floats, 16B mult)
#define WBUF (CO * WROW)            // 2368 floats
#define XBUF (4 * 3 * 80)           // 960 floats: [bquad][row][col*4 + bl]
#define BQS  240                    // bquad stride (floats)

#define WOSTRIDE (CIN * OH_ * OW_ * 9)   // weight float stride per o
#define WCSTRIDE (OH_ * OW_ * 9)         // weight float stride per c
#define XCSTRIDE (H_ * W_)               // x float stride per c

#define NOUT (B_ * CO * OH_ * OW_)       // 984064 floats (divisible by 4)

__device__ __align__(16) float g_scratch[3][NOUT];

__device__ __forceinline__ void ffma2(unsigned long long& d,
                                      unsigned long long a,
                                      unsigned long long b) {
    asm("fma.rn.f32x2 %0, %1, %2, %0;" : "+l"(d) : "l"(a), "l"(b));
}

__device__ __forceinline__ unsigned long long bcast2(float v) {
    unsigned long long p;
    asm("mov.b64 %0, {%1, %1};" : "=l"(p) : "f"(v));
    return p;
}

__device__ __forceinline__ void cp_async16(uint32_t dst, const float* src) {
    asm volatile("cp.async.cg.shared.global [%0], [%1], 16;\n"
                 :: "r"(dst), "l"(src));
}

__device__ __forceinline__ void cp_async4(uint32_t dst, const float* src, int sz) {
    asm volatile("cp.async.ca.shared.global [%0], [%1], 4, %2;\n"
                 :: "r"(dst), "l"(src), "r"(sz));
}

__global__ __launch_bounds__(256)
void sum_kernel(float* __restrict__ out) {
    const int i = blockIdx.x * blockDim.x + threadIdx.x;
    if (i < NOUT / 4) {
        float4 a = reinterpret_cast<float4*>(out)[i];
        float4 s0 = reinterpret_cast<const float4*>(g_scratch[0])[i];
        float4 s1 = reinterpret_cast<const float4*>(g_scratch[1])[i];
        float4 s2 = reinterpret_cast<const float4*>(g_scratch[2])[i];
        // fixed order: ((out + s0) + s1) + s2  -> deterministic
        a.x = ((a.x + s0.x) + s1.x) + s2.x;
        a.y = ((a.y + s0.y) + s1.y) + s2.y;
        a.z = ((a.z + s0.z) + s1.z) + s2.z;
        a.w = ((a.w + s0.w) + s1.w) + s2.w;
        reinterpret_cast<float4*>(out)[i] = a;
    }
}

__global__ __launch_bounds__(NT, 5)
void lc2d_kernel(const float* __restrict__ xin,
                 const float* __restrict__ wgt,
                 float* __restrict__ out) {
    __shared__ __align__(16) float sh_w[3 * WBUF];
    __shared__ __align__(16) float sh_x[3 * XBUF];

    const int tid = threadIdx.x;
    const int xl  = tid & 15;
    const int grp = tid >> 4;      // 0..7
    const int bh  = grp & 1;       // b half
    const int ob  = grp >> 1;      // o group

    const int y  = blockIdx.y;
    const int x0 = blockIdx.x * TX;
    const int xt = min(TX, OW_ - x0);       // 16 or 14
    const int zz = blockIdx.z;
    const int c0 = zz * NC;
    const int sh = 2 * (y & 1);             // uniform 16B-alignment shift

    const uint32_t shw_base = (uint32_t)__cvta_generic_to_shared(sh_w);
    const uint32_t shx_base = (uint32_t)__cvta_generic_to_shared(sh_x);

    // ---- weight staging descriptors (16B chunks, 5 slots) ----
    const int rowch  = (xt == TX) ? 37 : 32;
    const int nchunk = CO * rowch;
    const float* wcbase = wgt + (((c0 * OH_ + y) * OW_ + x0) * 9) - sh;

    int      wsoff[5];
    uint32_t wdst[5];
    bool     wok[5];
    #pragma unroll
    for (int n = 0; n < 5; ++n) {
        int m = tid + NT * n;
        wok[n] = (m < nchunk);
        int o   = m / rowch;
        int ci4 = (m - o * rowch) * 4;
        if (o > 15) { o = 15; ci4 = 0; }
        wsoff[n] = o * WOSTRIDE + ci4;
        wdst[n]  = (uint32_t)(o * WROW + ci4) * 4;
    }

    // ---- x staging descriptors (4B, b-quad interleaved, 7 slots) ----
    int      xsrcoff[7], xsz[7];
    uint32_t xdst[7];
    bool     xvalid[7];
    #pragma unroll
    for (int n = 0; n < 7; ++n) {
        int m = tid + NT * n;
        xvalid[n] = (m < B_ * 54);
        int b   = m / 54;
        int rem = m - b * 54;
        int r   = rem / 18;
        int cc  = rem - r * 18;
        if (!xvalid[n]) { b = 0; r = 0; cc = 0; }
        bool ok = xvalid[n] && (x0 + cc < W_);
        xsrcoff[n] = (b * CIN) * XCSTRIDE + r * W_ + cc;
        xsz[n]     = ok ? 4 : 0;
        xdst[n] = (uint32_t)((b >> 2) * BQS + r * 80 + cc * 4 + (b & 3)) * 4;
    }
    const float* xbase = xin + (c0 * H_ + y) * W_ + x0;

    unsigned long long acc[4][2][2];    // [oo][q][pair]: b=(bh*2+q)*4+2*pair
    #pragma unroll
    for (int oo = 0; oo < 4; ++oo)
        #pragma unroll
        for (int q = 0; q < 2; ++q) { acc[oo][q][0] = 0ull; acc[oo][q][1] = 0ull; }

    auto stage = [&](int buf, int ci) {
        uint32_t wb = shw_base + (uint32_t)buf * (WBUF * 4);
        const float* wc = wcbase + ci * WCSTRIDE;
        #pragma unroll
        for (int n = 0; n < 5; ++n)
            if (wok[n]) cp_async16(wb + wdst[n], wc + wsoff[n]);
        uint32_t xb = shx_base + (uint32_t)buf * (XBUF * 4);
        const float* xc = xbase + ci * XCSTRIDE;
        #pragma unroll
        for (int n = 0; n < 7; ++n)
            if (xvalid[n])
                cp_async4(xb + xdst[n], xc + xsrcoff[n], xsz[n]);
        asm volatile("cp.async.commit_group;\n" ::: "memory");
    };

    stage(0, 0);
    stage(1, 1);

    int rd = 0;
    #pragma unroll 1
    for (int ci = 0; ci < NC; ++ci) {
        if (ci < NC - 1) {
            asm volatile("cp.async.wait_group 1;\n" ::: "memory");
        } else {
            asm volatile("cp.async.wait_group 0;\n" ::: "memory");
        }
        __syncthreads();

        if (ci + 2 < NC) {
            int st = rd - 1; if (st < 0) st += 3;
            stage(st, ci + 2);
        }

        const float* swb = sh_w + rd * WBUF + sh;
        const float* sxb = sh_x + rd * XBUF + bh * (2 * BQS);

        #pragma unroll
        for (int k = 0; k < 9; ++k) {
            const int i = k / 3;
            const int j = k - i * 3;
            const float* xp = &sxb[i * 80 + (xl + j) * 4];
            ulonglong2 xq0 = *reinterpret_cast<const ulonglong2*>(xp);
            ulonglong2 xq1 = *reinterpret_cast<const ulonglong2*>(xp + BQS);
            #pragma unroll
            for (int oo = 0; oo < 4; ++oo) {
                float wv = swb[(ob * 4 + oo) * WROW + xl * 9 + k];
                unsigned long long wb2 = bcast2(wv);
                ffma2(acc[oo][0][0], xq0.x, wb2);
                ffma2(acc[oo][0][1], xq0.y, wb2);
                ffma2(acc[oo][1][0], xq1.x, wb2);
                ffma2(acc[oo][1][1], xq1.y, wb2);
            }
        }

        ++rd; if (rd == 3) rd = 0;
    }

    // ---- epilogue: plain STG of partials (no atomics, no memset) ----
    float* dst = (zz == 0) ? out : g_scratch[zz - 1];
    if (xl < xt) {
        #pragma unroll
        for (int oo = 0; oo < 4; ++oo) {
            const int o = ob * 4 + oo;
            #pragma unroll
            for (int q = 0; q < 2; ++q) {
                const int bq = (bh * 2 + q) * 4;
                #pragma unroll
                for (int p = 0; p < 2; ++p) {
                    float lo, hi;
                    asm("mov.b64 {%0, %1}, %2;"
                        : "=f"(lo), "=f"(hi) : "l"(acc[oo][q][p]));
                    const int b = bq + 2 * p;
                    dst[((b * CO + o)       * OH_ + y) * OW_ + x0 + xl] = lo;
                    dst[(((b + 1) * CO + o) * OH_ + y) * OW_ + x0 + xl] = hi;
                }
            }
        }
    }
}

extern "C" void kernel_launch(void* const* d_in, const int* in_sizes, int n_in,
                              void* d_out, int out_size) {
    const float* x = (const float*)d_in[0];
    const float* w = (const float*)d_in[1];
    float* out = (float*)d_out;

    dim3 grid((OW_ + TX - 1) / TX, OH_, 4);   // (4, 62, 4) = 992 blocks
    lc2d_kernel<<<grid, NT>>>(x, w, out);

    // out += s0 + s1 + s2 (fixed order, deterministic)
    sum_kernel<<<(NOUT / 4 + 255) / 256, 256>>>(out);
}

// round 13
// speedup vs baseline: 1.0770x; 1.0193x over previous
#include <cuda_runtime.h>
#include <cuda_bf16.h>
#include <cstdint>

// LocallyConnected2d: out[b,o,y,x] = sum_{c,k} x[b,c,y+i,x+j] * w[o,c,y,x,k]
// B=16, C_IN=16, C_OUT=16, H=W=64, OH=OW=62, K=3x3.
//
// R13 = R12 main kernel unchanged (R9 compute core + atomic-free STG
// partials: z=0 -> out, z=1..3 -> __device__ scratch) + high-MLP reduction
// kernel: 4 float4 quads per thread (16 independent loads in flight),
// streaming .cs loads/stores. Fixed-order sum -> bitwise deterministic.

#define B_  16
#define CIN 16
#define CO  16
#define H_  64
#define W_  64
#define OH_ 62
#define OW_ 62
#define TX  16
#define NT  128

#define NC  4                       // channels per block (4-way c split)
#define WROW 148                    // weight smem row stride (floats, 16B mult)
#define WBUF (CO * WROW)            // 2368 floats
#define XBUF (4 * 3 * 80)           // 960 floats: [bquad][row][col*4 + bl]
#define BQS  240                    // bquad stride (floats)

#define WOSTRIDE (CIN * OH_ * OW_ * 9)   // weight float stride per o
#define WCSTRIDE (OH_ * OW_ * 9)         // weight float stride per c
#define XCSTRIDE (H_ * W_)               // x float stride per c

#define NOUT (B_ * CO * OH_ * OW_)       // 984064 floats (divisible by 4)
#define N4   (NOUT / 4)                  // 246016 float4s

__device__ __align__(16) float g_scratch[3][NOUT];

__device__ __forceinline__ void ffma2(unsigned long long& d,
                                      unsigned long long a,
                                      unsigned long long b) {
    asm("fma.rn.f32x2 %0, %1, %2, %0;" : "+l"(d) : "l"(a), "l"(b));
}

__device__ __forceinline__ unsigned long long bcast2(float v) {
    unsigned long long p;
    asm("mov.b64 %0, {%1, %1};" : "=l"(p) : "f"(v));
    return p;
}

__device__ __forceinline__ void cp_async16(uint32_t dst, const float* src) {
    asm volatile("cp.async.cg.shared.global [%0], [%1], 16;\n"
                 :: "r"(dst), "l"(src));
}

__device__ __forceinline__ void cp_async4(uint32_t dst, const float* src, int sz) {
    asm volatile("cp.async.ca.shared.global [%0], [%1], 4, %2;\n"
                 :: "r"(dst), "l"(src), "r"(sz));
}

__device__ __forceinline__ float4 ldcs4(const float4* p) {
    float4 v;
    asm volatile("ld.global.cs.v4.f32 {%0,%1,%2,%3}, [%4];"
                 : "=f"(v.x), "=f"(v.y), "=f"(v.z), "=f"(v.w) : "l"(p));
    return v;
}

__device__ __forceinline__ void stcs4(float4* p, float4 v) {
    asm volatile("st.global.cs.v4.f32 [%0], {%1,%2,%3,%4};"
                 :: "l"(p), "f"(v.x), "f"(v.y), "f"(v.z), "f"(v.w) : "memory");
}

// 4 quads per thread, 16 independent loads in flight, streaming.
__global__ __launch_bounds__(256)
void sum_kernel(float* __restrict__ out) {
    const int base = blockIdx.x * 1024 + threadIdx.x;

    float4 a[4], s0[4], s1[4], s2[4];
    bool ok[4];
    #pragma unroll
    for (int q = 0; q < 4; ++q) {
        const int i = base + q * 256;
        ok[q] = (i < N4);
        const int ii = ok[q] ? i : 0;
        a[q]  = ldcs4(reinterpret_cast<const float4*>(out) + ii);
        s0[q] = ldcs4(reinterpret_cast<const float4*>(g_scratch[0]) + ii);
        s1[q] = ldcs4(reinterpret_cast<const float4*>(g_scratch[1]) + ii);
        s2[q] = ldcs4(reinterpret_cast<const float4*>(g_scratch[2]) + ii);
    }
    #pragma unroll
    for (int q = 0; q < 4; ++q) {
        if (ok[q]) {
            float4 r;
            r.x = ((a[q].x + s0[q].x) + s1[q].x) + s2[q].x;
            r.y = ((a[q].y + s0[q].y) + s1[q].y) + s2[q].y;
            r.z = ((a[q].z + s0[q].z) + s1[q].z) + s2[q].z;
            r.w = ((a[q].w + s0[q].w) + s1[q].w) + s2[q].w;
            stcs4(reinterpret_cast<float4*>(out) + base + q * 256, r);
        }
    }
}

__global__ __launch_bounds__(NT, 5)
void lc2d_kernel(const float* __restrict__ xin,
                 const float* __restrict__ wgt,
                 float* __restrict__ out) {
    __shared__ __align__(16) float sh_w[3 * WBUF];
    __shared__ __align__(16) float sh_x[3 * XBUF];

    const int tid = threadIdx.x;
    const int xl  = tid & 15;
    const int grp = tid >> 4;      // 0..7
    const int bh  = grp & 1;       // b half
    const int ob  = grp >> 1;      // o group

    const int y  = blockIdx.y;
    const int x0 = blockIdx.x * TX;
    const int xt = min(TX, OW_ - x0);       // 16 or 14
    const int zz = blockIdx.z;
    const int c0 = zz * NC;
    const int sh = 2 * (y & 1);             // uniform 16B-alignment shift

    const uint32_t shw_base = (uint32_t)__cvta_generic_to_shared(sh_w);
    const uint32_t shx_base = (uint32_t)__cvta_generic_to_shared(sh_x);

    // ---- weight staging descriptors (16B chunks, 5 slots) ----
    const int rowch  = (xt == TX) ? 37 : 32;
    const int nchunk = CO * rowch;
    const float* wcbase = wgt + (((c0 * OH_ + y) * OW_ + x0) * 9) - sh;

    int      wsoff[5];
    uint32_t wdst[5];
    bool     wok[5];
    #pragma unroll
    for (int n = 0; n < 5; ++n) {
        int m = tid + NT * n;
        wok[n] = (m < nchunk);
        int o   = m / rowch;
        int ci4 = (m - o * rowch) * 4;
        if (o > 15) { o = 15; ci4 = 0; }
        wsoff[n] = o * WOSTRIDE + ci4;
        wdst[n]  = (uint32_t)(o * WROW + ci4) * 4;
    }

    // ---- x staging descriptors (4B, b-quad interleaved, 7 slots) ----
    int      xsrcoff[7], xsz[7];
    uint32_t xdst[7];
    bool     xvalid[7];
    #pragma unroll
    for (int n = 0; n < 7; ++n) {
        int m = tid + NT * n;
        xvalid[n] = (m < B_ * 54);
        int b   = m / 54;
        int rem = m - b * 54;
        int r   = rem / 18;
        int cc  = rem - r * 18;
        if (!xvalid[n]) { b = 0; r = 0; cc = 0; }
        bool ok = xvalid[n] && (x0 + cc < W_);
        xsrcoff[n] = (b * CIN) * XCSTRIDE + r * W_ + cc;
        xsz[n]     = ok ? 4 : 0;
        xdst[n] = (uint32_t)((b >> 2) * BQS + r * 80 + cc * 4 + (b & 3)) * 4;
    }
    const float* xbase = xin + (c0 * H_ + y) * W_ + x0;

    unsigned long long acc[4][2][2];    // [oo][q][pair]: b=(bh*2+q)*4+2*pair
    #pragma unroll
    for (int oo = 0; oo < 4; ++oo)
        #pragma unroll
        for (int q = 0; q < 2; ++q) { acc[oo][q][0] = 0ull; acc[oo][q][1] = 0ull; }

    auto stage = [&](int buf, int ci) {
        uint32_t wb = shw_base + (uint32_t)buf * (WBUF * 4);
        const float* wc = wcbase + ci * WCSTRIDE;
        #pragma unroll
        for (int n = 0; n < 5; ++n)
            if (wok[n]) cp_async16(wb + wdst[n], wc + wsoff[n]);
        uint32_t xb = shx_base + (uint32_t)buf * (XBUF * 4);
        const float* xc = xbase + ci * XCSTRIDE;
        #pragma unroll
        for (int n = 0; n < 7; ++n)
            if (xvalid[n])
                cp_async4(xb + xdst[n], xc + xsrcoff[n], xsz[n]);
        asm volatile("cp.async.commit_group;\n" ::: "memory");
    };

    stage(0, 0);
    stage(1, 1);

    int rd = 0;
    #pragma unroll 1
    for (int ci = 0; ci < NC; ++ci) {
        if (ci < NC - 1) {
            asm volatile("cp.async.wait_group 1;\n" ::: "memory");
        } else {
            asm volatile("cp.async.wait_group 0;\n" ::: "memory");
        }
        __syncthreads();

        if (ci + 2 < NC) {
            int st = rd - 1; if (st < 0) st += 3;
            stage(st, ci + 2);
        }

        const float* swb = sh_w + rd * WBUF + sh;
        const float* sxb = sh_x + rd * XBUF + bh * (2 * BQS);

        #pragma unroll
        for (int k = 0; k < 9; ++k) {
            const int i = k / 3;
            const int j = k - i * 3;
            const float* xp = &sxb[i * 80 + (xl + j) * 4];
            ulonglong2 xq0 = *reinterpret_cast<const ulonglong2*>(xp);
            ulonglong2 xq1 = *reinterpret_cast<const ulonglong2*>(xp + BQS);
            #pragma unroll
            for (int oo = 0; oo < 4; ++oo) {
                float wv = swb[(ob * 4 + oo) * WROW + xl * 9 + k];
                unsigned long long wb2 = bcast2(wv);
                ffma2(acc[oo][0][0], xq0.x, wb2);
                ffma2(acc[oo][0][1], xq0.y, wb2);
                ffma2(acc[oo][1][0], xq1.x, wb2);
                ffma2(acc[oo][1][1], xq1.y, wb2);
            }
        }

        ++rd; if (rd == 3) rd = 0;
    }

    // ---- epilogue: plain STG of partials (no atomics, no memset) ----
    float* dst = (zz == 0) ? out : g_scratch[zz - 1];
    if (xl < xt) {
        #pragma unroll
        for (int oo = 0; oo < 4; ++oo) {
            const int o = ob * 4 + oo;
            #pragma unroll
            for (int q = 0; q < 2; ++q) {
                const int bq = (bh * 2 + q) * 4;
                #pragma unroll
                for (int p = 0; p < 2; ++p) {
                    float lo, hi;
                    asm("mov.b64 {%0, %1}, %2;"
                        : "=f"(lo), "=f"(hi) : "l"(acc[oo][q][p]));
                    const int b = bq + 2 * p;
                    dst[((b * CO + o)       * OH_ + y) * OW_ + x0 + xl] = lo;
                    dst[(((b + 1) * CO + o) * OH_ + y) * OW_ + x0 + xl] = hi;
                }
            }
        }
    }
}

extern "C" void kernel_launch(void* const* d_in, const int* in_sizes, int n_in,
                              void* d_out, int out_size) {
    const float* x = (const float*)d_in[0];
    const float* w = (const float*)d_in[1];
    float* out = (float*)d_out;

    dim3 grid((OW_ + TX - 1) / TX, OH_, 4);   // (4, 62, 4) = 992 blocks
    lc2d_kernel<<<grid, NT>>>(x, w, out);

    // out += s0 + s1 + s2 (fixed order, deterministic)
    sum_kernel<<<(N4 + 1023) / 1024, 256>>>(out);
}